// round 17
// baseline (speedup 1.0000x reference)
#include <cuda_runtime.h>

// LIF SNN scan: T=1024 timesteps, B*N = 65536 independent columns.
// out layout: [ spikes (T*BN) | v_final (BN) | i_final (BN) ]
// R17: last untested interior point — ring depth PF=48 (between the measured
// 32-peak and the 64-regression). 48 < M_max~55/warp LDG accept cap, so the
// hard-stall mechanism that sank PF=64 cannot fire; in-flight rises 56->84
// KB/SM (3.3x latency knee). Inner step byte-identical to R9 (R14 proved the
// body must not be perturbed). 48 does not divide 1024 -> explicit tail:
// main loop covers t<960 (prefetch <=1007, in-bounds), then 16 steps with
// reload of t=1008..1023, then drain 32+16. No predication, no clamping.

#define T_STEPS 1024
#define BN      65536
#define NCOL2   (BN / 2)    // float2 columns
#define PF      48

#define LIF_STEP(XT, TOUT)                                  \
    do {                                                    \
        const float2 xt_ = (XT);                            \
        float2 z_;                                          \
        const float vd0_ = fmaf(0.1f, c0 - v0, v0);         \
        const bool  f0_  = (vd0_ > 1.0f);                   \
        z_.x = f0_ ? 1.0f : 0.0f;                           \
        v0   = f0_ ? 0.0f : vd0_;                           \
        c0   = fmaf(c0, 0.8f, xt_.x);                       \
        const float vd1_ = fmaf(0.1f, c1 - v1, v1);         \
        const bool  f1_  = (vd1_ > 1.0f);                   \
        z_.y = f1_ ? 1.0f : 0.0f;                           \
        v1   = f1_ ? 0.0f : vd1_;                           \
        c1   = fmaf(c1, 0.8f, xt_.y);                       \
        zp[(long)(TOUT) * NCOL2] = z_;                      \
    } while (0)

__global__ __launch_bounds__(64, 4)
void snn_lif_kernel(const float2* __restrict__ x, float2* __restrict__ out) {
    const int idx = blockIdx.x * blockDim.x + threadIdx.x;  // float2-column id
    const float2* xp = x + idx;
    float2*       zp = out + idx;

    float v0 = 0.0f, v1 = 0.0f;     // membrane potentials
    float c0 = 0.0f, c1 = 0.0f;     // synaptic currents

    // prologue: fill the prefetch ring (48 independent LDG.64 in flight)
    float2 xbuf[PF];
    #pragma unroll
    for (int j = 0; j < PF; ++j)
        xbuf[j] = __ldg(xp + (long)j * NCOL2);

    // main loop: t0 = 0, 48, ..., 912 (20 iterations, consumes t = 0..959;
    // last prefetch t = 912+48+47 = 1007 <= 1023, always in bounds)
    for (int t0 = 0; t0 <= T_STEPS - 2 * PF + 16; t0 += PF) {
        #pragma unroll
        for (int j = 0; j < PF; ++j) {
            const float2 xt = xbuf[j];
            xbuf[j] = __ldg(xp + (long)(t0 + PF + j) * NCOL2);
            LIF_STEP(xt, t0 + j);
        }
    }
    // here xbuf[j] holds t = 960 + j for j = 0..47

    // tail A: consume t = 960..975 from slots 0..15, reload them with 1008..1023
    #pragma unroll
    for (int j = 0; j < 16; ++j) {
        const float2 xt = xbuf[j];
        xbuf[j] = __ldg(xp + (long)(1008 + j) * NCOL2);
        LIF_STEP(xt, 960 + j);
    }

    // tail B: drain t = 976..1007 from slots 16..47
    #pragma unroll
    for (int j = 16; j < PF; ++j) {
        const float2 xt = xbuf[j];
        LIF_STEP(xt, 960 + j);
    }

    // tail C: drain t = 1008..1023 from slots 0..15
    #pragma unroll
    for (int j = 0; j < 16; ++j) {
        const float2 xt = xbuf[j];
        LIF_STEP(xt, 1008 + j);
    }

    // final state after the full scan: v then i, each BN floats (NCOL2 float2)
    float2 vf; vf.x = v0; vf.y = v1;
    float2 cf; cf.x = c0; cf.y = c1;
    out[(long)T_STEPS * NCOL2 + idx]          = vf;
    out[(long)T_STEPS * NCOL2 + NCOL2 + idx]  = cf;
}

extern "C" void kernel_launch(void* const* d_in, const int* in_sizes, int n_in,
                              void* d_out, int out_size) {
    const float2* x   = (const float2*)d_in[0];
    float2*       out = (float2*)d_out;
    (void)in_sizes; (void)n_in; (void)out_size;

    snn_lif_kernel<<<NCOL2 / 64, 64>>>(x, out);
}